// round 4
// baseline (speedup 1.0000x reference)
#include <cuda_runtime.h>
#include <math.h>

// Problem dims
#define Bc   128
#define Nch  128
#define Tc   336
#define Hc   64
#define Kc   4
#define Fc   720
#define BNT  (Bc*Nch)          // 16384

// ---------------- scratch (device globals; no allocs allowed) ----------------
__device__ float g_H1[BNT*128];        // mu|sg hidden, relu'd   (8 MB)
__device__ float g_Hw[BNT*Kc*64];      // wg hidden, relu'd      (16 MB)
__device__ float g_Hf[BNT*Fc];         // fitter hidden, relu'd  (45 MB, reused per fitter)
__device__ float g_spmu[BNT*Kc];
__device__ float g_spsg[BNT*Kc];
__device__ float g_w[BNT*Kc];
__device__ float g_coef[BNT*8];        // 7 coeffs, stride 8
__device__ float g_S[64 + 4*Fc];       // rowsums: wg_W1 then f0..f3 W1

__device__ __forceinline__ float softplus_f(float x) {
    return fmaxf(x, 0.f) + log1pf(expf(-fabsf(x)));
}

// ---------------- rowsum: S[r] = sum_t W[r,t] ----------------
__global__ void rowsum_kernel(const float* __restrict__ W, float* __restrict__ S, int rows) {
    int warp = (blockIdx.x * blockDim.x + threadIdx.x) >> 5;
    int lane = threadIdx.x & 31;
    if (warp >= rows) return;
    const float* row = W + (long)warp * Tc;
    float s = 0.f;
    for (int j = lane; j < Tc; j += 32) s += row[j];
    #pragma unroll
    for (int o = 16; o; o >>= 1) s += __shfl_xor_sync(0xffffffffu, s, o);
    if (lane == 0) S[warp] = s;
}

// ---------------- tiled SGEMM: C[m,n] = epilogue( A[m,:] . W[n,:] ) ----------------
// A row-major [M, Tc] with row stride lda. W row-major [Ncols, Tc].
// MODE 0: C = relu(acc + b1[n])
// MODE 1: C = relu(b1[n] + spmu[idx]*S[n] + spsg[idx]*acc), idx = m*sp_mul + sp_add
#define BM 128
#define BN 64
#define BK 8

template<int MODE>
__global__ __launch_bounds__(256)
void gemm_kernel(const float* __restrict__ A, int lda,
                 const float* __restrict__ W, int Ncols,
                 float* __restrict__ C, int ldc,
                 const float* __restrict__ b1,
                 const float* __restrict__ S,
                 const float* __restrict__ spmu,
                 const float* __restrict__ spsg,
                 int sp_mul, int sp_add)
{
    __shared__ __align__(16) float As[BK][BM + 4];
    __shared__ __align__(16) float Ws[BK][BN + 4];

    const int t  = threadIdx.x;
    const int tx = t & 15;        // 16 col-groups of 4
    const int ty = t >> 4;        // 16 row-groups of 8
    const int m0 = blockIdx.y * BM;
    const int n0 = blockIdx.x * BN;

    float acc[8][4];
    #pragma unroll
    for (int i = 0; i < 8; i++)
        #pragma unroll
        for (int j = 0; j < 4; j++) acc[i][j] = 0.f;

    const int a_m = t >> 1, a_k = (t & 1) * 4;
    const bool w_act = (t < 128);
    const int w_n = t >> 1, w_k = a_k;
    const float* Aptr = A + (long)(m0 + a_m) * lda + a_k;
    const bool w_valid = w_act && (n0 + w_n < Ncols);
    const float* Wptr = W + (long)(n0 + w_n) * Tc + w_k;

    for (int k0 = 0; k0 < Tc; k0 += BK) {
        float4 av = *(const float4*)(Aptr + k0);
        float4 wv = make_float4(0.f, 0.f, 0.f, 0.f);
        if (w_valid) wv = *(const float4*)(Wptr + k0);

        __syncthreads();
        As[a_k + 0][a_m] = av.x; As[a_k + 1][a_m] = av.y;
        As[a_k + 2][a_m] = av.z; As[a_k + 3][a_m] = av.w;
        if (w_act) {
            Ws[w_k + 0][w_n] = wv.x; Ws[w_k + 1][w_n] = wv.y;
            Ws[w_k + 2][w_n] = wv.z; Ws[w_k + 3][w_n] = wv.w;
        }
        __syncthreads();

        #pragma unroll
        for (int kk = 0; kk < BK; kk++) {
            float4 bv = *(const float4*)&Ws[kk][tx * 4];
            float4 a0 = *(const float4*)&As[kk][ty * 8];
            float4 a1 = *(const float4*)&As[kk][ty * 8 + 4];
            float ar[8] = {a0.x, a0.y, a0.z, a0.w, a1.x, a1.y, a1.z, a1.w};
            float br[4] = {bv.x, bv.y, bv.z, bv.w};
            #pragma unroll
            for (int i = 0; i < 8; i++)
                #pragma unroll
                for (int j = 0; j < 4; j++)
                    acc[i][j] += ar[i] * br[j];
        }
    }

    #pragma unroll
    for (int i = 0; i < 8; i++) {
        const int m = m0 + ty * 8 + i;
        float smu = 0.f, ssg = 0.f;
        if (MODE == 1) {
            int idx = m * sp_mul + sp_add;
            smu = spmu[idx]; ssg = spsg[idx];
        }
        #pragma unroll
        for (int j = 0; j < 4; j++) {
            const int n = n0 + tx * 4 + j;
            if (n < Ncols) {
                float v;
                if (MODE == 0) v = acc[i][j] + __ldg(&b1[n]);
                else           v = __ldg(&b1[n]) + smu * __ldg(&S[n]) + ssg * acc[i][j];
                C[(long)m * ldc + n] = fmaxf(v, 0.f);
            }
        }
    }
}

// ---------------- mu/sigma second layer + softplus ----------------
__global__ void musig2_kernel(const float* __restrict__ muW2, const float* __restrict__ mub2,
                              const float* __restrict__ sgW2, const float* __restrict__ sgb2)
{
    int row  = blockIdx.x * 8 + (threadIdx.x >> 5);
    int lane = threadIdx.x & 31;
    if (row >= BNT) return;
    const float* h = g_H1 + (long)row * 128;
    float hm0 = h[lane], hm1 = h[32 + lane];
    float hs0 = h[64 + lane], hs1 = h[96 + lane];
    #pragma unroll
    for (int o = 0; o < 4; o++) {
        float vm = hm0 * muW2[o * 64 + lane] + hm1 * muW2[o * 64 + 32 + lane];
        float vs = hs0 * sgW2[o * 64 + lane] + hs1 * sgW2[o * 64 + 32 + lane];
        #pragma unroll
        for (int s = 16; s; s >>= 1) {
            vm += __shfl_xor_sync(0xffffffffu, vm, s);
            vs += __shfl_xor_sync(0xffffffffu, vs, s);
        }
        if (lane == 0) {
            g_spmu[row * 4 + o] = softplus_f(vm + mub2[o]);
            g_spsg[row * 4 + o] = softplus_f(vs + sgb2[o]);
        }
    }
}

// ---------------- wg second layer + softmax over K ----------------
__global__ void wglogit_kernel(const float* __restrict__ W2, const float* __restrict__ b2)
{
    int bn   = blockIdx.x * 8 + (threadIdx.x >> 5);
    int lane = threadIdx.x & 31;
    if (bn >= BNT) return;
    float lg[4];
    #pragma unroll
    for (int k = 0; k < 4; k++) {
        const float* h = g_Hw + (long)(bn * 4 + k) * 64;
        float v = h[lane] * W2[lane] + h[32 + lane] * W2[32 + lane];
        #pragma unroll
        for (int s = 16; s; s >>= 1) v += __shfl_xor_sync(0xffffffffu, v, s);
        lg[k] = v + b2[0];
    }
    float m = fmaxf(fmaxf(lg[0], lg[1]), fmaxf(lg[2], lg[3]));
    float e0 = expf(lg[0] - m), e1 = expf(lg[1] - m), e2 = expf(lg[2] - m), e3 = expf(lg[3] - m);
    float inv = 1.f / (e0 + e1 + e2 + e3);
    if (lane == 0) {
        g_w[bn * 4 + 0] = e0 * inv; g_w[bn * 4 + 1] = e1 * inv;
        g_w[bn * 4 + 2] = e2 * inv; g_w[bn * 4 + 3] = e3 * inv;
    }
}

// ---------------- fitter second layer: coeffs ----------------
__global__ void coeffs_kernel(const float* __restrict__ W2, const float* __restrict__ b2,
                              int deg, int off)
{
    int bn   = blockIdx.x * 8 + (threadIdx.x >> 5);
    int lane = threadIdx.x & 31;
    if (bn >= BNT) return;
    const float* h = g_Hf + (long)bn * Fc;
    for (int d = 0; d < deg; d++) {
        const float* w2 = W2 + (long)d * Fc;
        float s = 0.f;
        for (int f = lane; f < Fc; f += 32) s += h[f] * w2[f];
        #pragma unroll
        for (int o = 16; o; o >>= 1) s += __shfl_xor_sync(0xffffffffu, s, o);
        if (lane == 0) g_coef[bn * 8 + off + d] = s + b2[d];
    }
}

// ---------------- final: polynomial eval + mixture + transpose ----------------
#define FCHUNK 48
__global__ void final_kernel(float* __restrict__ out)
{
    int b  = blockIdx.y;
    int f0 = blockIdx.x * FCHUNK;
    int n  = threadIdx.x;
    int bn = b * Nch + n;
    float w0 = g_w[bn * 4 + 0], w1 = g_w[bn * 4 + 1], w2 = g_w[bn * 4 + 2], w3 = g_w[bn * 4 + 3];
    float c0 = g_coef[bn * 8 + 0];
    float c1 = g_coef[bn * 8 + 1], c2 = g_coef[bn * 8 + 2];
    float c3 = g_coef[bn * 8 + 3], c4 = g_coef[bn * 8 + 4], c5 = g_coef[bn * 8 + 5];
    float c6 = g_coef[bn * 8 + 6];
    #pragma unroll 4
    for (int fi = 0; fi < FCHUNK; fi++) {
        int f = f0 + fi;
        float tt = (float)f * (1.f / 719.f);
        float t2 = tt * tt, t3 = t2 * tt;
        float p0 = c0 + 0.5f * tt;
        float p1 = c1 + c2 * tt + 0.5f * t2;
        float p2 = c3 + c4 * tt + c5 * t2 + 0.5f * t3;
        float p3 = c6 - 0.5f * tt;
        out[((long)b * Fc + f) * Nch + n] = w0 * p0 + w1 * p1 + w2 * p2 + w3 * p3;
    }
}

// ---------------- launch ----------------
extern "C" void kernel_launch(void* const* d_in, const int* in_sizes, int n_in,
                              void* d_out, int out_size)
{
    const float* x     = (const float*)d_in[0];
    const float* eps   = (const float*)d_in[1];
    const float* muW1  = (const float*)d_in[2];
    const float* mub1  = (const float*)d_in[3];
    const float* muW2  = (const float*)d_in[4];
    const float* mub2  = (const float*)d_in[5];
    const float* sgW1  = (const float*)d_in[6];
    const float* sgb1  = (const float*)d_in[7];
    const float* sgW2  = (const float*)d_in[8];
    const float* sgb2  = (const float*)d_in[9];
    const float* wgW1  = (const float*)d_in[10];
    const float* wgb1  = (const float*)d_in[11];
    const float* wgW2  = (const float*)d_in[12];
    const float* wgb2  = (const float*)d_in[13];
    const float* fW1[4] = {(const float*)d_in[14], (const float*)d_in[18],
                           (const float*)d_in[22], (const float*)d_in[26]};
    const float* fb1[4] = {(const float*)d_in[15], (const float*)d_in[19],
                           (const float*)d_in[23], (const float*)d_in[27]};
    const float* fW2[4] = {(const float*)d_in[16], (const float*)d_in[20],
                           (const float*)d_in[24], (const float*)d_in[28]};
    const float* fb2[4] = {(const float*)d_in[17], (const float*)d_in[21],
                           (const float*)d_in[25], (const float*)d_in[29]};
    float* out = (float*)d_out;

    float* H1;  cudaGetSymbolAddress((void**)&H1,  g_H1);
    float* Hw;  cudaGetSymbolAddress((void**)&Hw,  g_Hw);
    float* Hf;  cudaGetSymbolAddress((void**)&Hf,  g_Hf);
    float* spm; cudaGetSymbolAddress((void**)&spm, g_spmu);
    float* sps; cudaGetSymbolAddress((void**)&sps, g_spsg);
    float* Sp;  cudaGetSymbolAddress((void**)&Sp,  g_S);

    // rowsums (wg + 4 fitters)
    rowsum_kernel<<<(64 * 32 + 255) / 256, 256>>>(wgW1, Sp, 64);
    for (int i = 0; i < 4; i++)
        rowsum_kernel<<<(Fc * 32 + 255) / 256, 256>>>(fW1[i], Sp + 64 + i * Fc, Fc);

    // mu / sigma hidden: x @ [muW1;sgW1]^T -> g_H1 [16384,128]
    {
        dim3 grid(1, BNT / BM);
        gemm_kernel<0><<<grid, 256>>>(x, Tc, muW1, Hc, H1,      128, mub1, nullptr, nullptr, nullptr, 0, 0);
        gemm_kernel<0><<<grid, 256>>>(x, Tc, sgW1, Hc, H1 + 64, 128, sgb1, nullptr, nullptr, nullptr, 0, 0);
    }
    musig2_kernel<<<BNT / 8, 256>>>(muW2, mub2, sgW2, sgb2);

    // wg hidden: eps [65536,336] -> g_Hw [65536,64]
    {
        dim3 grid(1, (BNT * Kc) / BM);
        gemm_kernel<1><<<grid, 256>>>(eps, Tc, wgW1, Hc, Hw, 64, wgb1, Sp, spm, sps, 1, 0);
    }
    wglogit_kernel<<<BNT / 8, 256>>>(wgW2, wgb2);

    // fitters
    static const int DEG[4] = {1, 2, 3, 1};
    static const int OFF[4] = {0, 1, 3, 6};
    for (int i = 0; i < 4; i++) {
        dim3 grid((Fc + BN - 1) / BN, BNT / BM);
        gemm_kernel<1><<<grid, 256>>>(eps + i * Tc, Kc * Tc, fW1[i], Fc, Hf, Fc,
                                      fb1[i], Sp + 64 + i * Fc, spm, sps, 4, i);
        coeffs_kernel<<<BNT / 8, 256>>>(fW2[i], fb2[i], DEG[i], OFF[i]);
    }

    // final mixture + transpose
    {
        dim3 grid(Fc / FCHUNK, Bc);
        final_kernel<<<grid, 128>>>(out);
    }
}